// round 9
// baseline (speedup 1.0000x reference)
#include <cuda_runtime.h>
#include <cstdint>
#include <math.h>

#define Bn 2048
#define Hn 8

namespace {
// SMEM byte offsets; all operand tiles use padded strides (bank-conflict-free)
constexpr int OFF_IDX = 0;                    // 128 int
constexpr int OFF_RED = 512;                  // 8 float
constexpr int OFF_XS  = 576;                  // fp32 [4][144] sum-exchange
constexpr int OFF_E   = 3072;                 // fp8 [128 f][128 k] stride 144
constexpr int OFF_W0  = OFF_E  + 128 * 144;   // fp8 [64 n][128 k] stride 144
constexpr int OFF_W1  = OFF_W0 + 64 * 144;    // fp8 [64 n][128 k]
constexpr int OFF_K   = OFF_W1 + 64 * 144;    // fp8 [128 f][64 p] stride 80
constexpr int OFF_V   = OFF_K  + 128 * 80;    // fp8 [64 p][128 f] stride 144
constexpr int OFF_QA  = OFF_V  + 64 * 144;    // fp8 [128 f][64 p] stride 80 (q, then att)
constexpr int SMEM_BYTES = OFF_QA + 128 * 80; // 69632 B -> 2 CTAs/SM

constexpr float SC_E  = 128.f;                 // E scale into fp8
constexpr float SC_W  = 8.f;                   // W scale into fp8
constexpr float SEXP  = 1.52587890625e-5f;     // 1/65536: scores de-scale
constexpr float IS_AV = 1.52587890625e-5f;     // 1/65536: AV de-scale
constexpr float IS_R  = 9.765625e-4f;          // 1/1024:  r de-scale
}

__device__ __forceinline__ uint32_t pack_fp8x2(float lo, float hi) {
    uint16_t r;
    asm("cvt.rn.satfinite.e4m3x2.f32 %0, %1, %2;" : "=h"(r) : "f"(hi), "f"(lo));
    return (uint32_t)r;
}
__device__ __forceinline__ uint32_t pack_fp8x4(float f0, float f1, float f2, float f3) {
    uint16_t lo, hi;
    asm("cvt.rn.satfinite.e4m3x2.f32 %0, %1, %2;" : "=h"(lo) : "f"(f1), "f"(f0));
    asm("cvt.rn.satfinite.e4m3x2.f32 %0, %1, %2;" : "=h"(hi) : "f"(f3), "f"(f2));
    return (uint32_t)lo | ((uint32_t)hi << 16);
}
__device__ __forceinline__ char fp8b(float x) { return (char)pack_fp8x2(x, 0.f); }

__device__ __forceinline__ void mma16832(float* c, const uint32_t* a, uint32_t b0, uint32_t b1) {
    asm volatile(
        "mma.sync.aligned.m16n8k32.row.col.f32.e4m3.e4m3.f32 "
        "{%0,%1,%2,%3}, {%4,%5,%6,%7}, {%8,%9}, {%0,%1,%2,%3};"
        : "+f"(c[0]), "+f"(c[1]), "+f"(c[2]), "+f"(c[3])
        : "r"(a[0]), "r"(a[1]), "r"(a[2]), "r"(a[3]), "r"(b0), "r"(b1));
}

// A fragment (m16 x k32 fp8) via 4 plain LDS.32: lane row = l>>2 (+8), k = 4*(l&3) (+16)
__device__ __forceinline__ void lda(uint32_t a[4], const char* base, int stride,
                                    int row, int kb, int lane) {
    const char* p = base + (row + (lane >> 2)) * stride + kb + 4 * (lane & 3);
    a[0] = *(const uint32_t*)p;
    a[1] = *(const uint32_t*)(p + 8 * stride);
    a[2] = *(const uint32_t*)(p + 16);
    a[3] = *(const uint32_t*)(p + 8 * stride + 16);
}

// C[16x64] = E[16x128] @ W[128x64] in fp8; A hoisted, B = 2 LDS.32 per mma
__device__ __forceinline__ void run_proj8(float acc[32], const uint32_t ea[4][4],
                                          const char* wb, int lane) {
#pragma unroll
    for (int i = 0; i < 32; i++) acc[i] = 0.f;
#pragma unroll
    for (int kt = 0; kt < 4; kt++) {
#pragma unroll
        for (int nt = 0; nt < 8; nt++) {
            const char* bp = wb + (nt * 8 + (lane >> 2)) * 144 + kt * 32 + 4 * (lane & 3);
            mma16832(&acc[nt * 4], ea[kt],
                     *(const uint32_t*)bp, *(const uint32_t*)(bp + 16));
        }
    }
}

// scatter a 16-row C tile (rows row+g, row+8+g; cols nt*8+2q+{0,1}) as fp8 pairs;
// even-odd lane shfl combines 4 bytes -> one STS.32 per (nt, half) on even lanes.
__device__ __forceinline__ void scatter_rows(char* dst, int stride, int row,
                                             const float* acc, float s, int lane) {
    char* r0 = dst + (row + (lane >> 2)) * stride + 2 * (lane & 3);
#pragma unroll
    for (int nt = 0; nt < 8; nt++) {
        uint32_t w0 = pack_fp8x2(acc[4 * nt]     * s, acc[4 * nt + 1] * s);
        uint32_t w1 = pack_fp8x2(acc[4 * nt + 2] * s, acc[4 * nt + 3] * s);
        uint32_t h0 = __shfl_down_sync(0xffffffffu, w0, 1);
        uint32_t h1 = __shfl_down_sync(0xffffffffu, w1, 1);
        if (!(lane & 1)) {
            *(uint32_t*)(r0 + nt * 8)               = w0 | (h0 << 16);
            *(uint32_t*)(r0 + 8 * stride + nt * 8)  = w1 | (h1 << 16);
        }
    }
}

// stage two W head-slices transposed -> fp8 [n][k]: threads 0-127 Wa->W0, 128-255 Wb->W1
__device__ __forceinline__ void stage_w2(char* sm, const float* Wa, const float* Wb,
                                         int h, int tid) {
    const float* W = (tid < 128) ? Wa : Wb;
    char* base = sm + ((tid < 128) ? OFF_W0 : OFF_W1);
    int t  = tid & 127;
    int n4 = (t & 15) * 4;
    int k0 = t >> 4;                        // 0..7
    const float* src = W + h * 64 + n4;
#pragma unroll
    for (int it = 0; it < 16; it++) {
        int k = k0 + it * 8;
        float4 v = *(const float4*)(src + (size_t)k * 512);
        uint32_t p = pack_fp8x4(v.x * SC_W, v.y * SC_W, v.z * SC_W, v.w * SC_W);
        base[(n4 + 0) * 144 + k] = (char)(p);
        base[(n4 + 1) * 144 + k] = (char)(p >> 8);
        base[(n4 + 2) * 144 + k] = (char)(p >> 16);
        base[(n4 + 3) * 144 + k] = (char)(p >> 24);
    }
}

__global__ __launch_bounds__(256, 2)
void autoint_fp8(const int*   __restrict__ feat_index,
                 const float* __restrict__ emb,
                 const float* __restrict__ Wq, const float* __restrict__ Wk,
                 const float* __restrict__ Wv, const float* __restrict__ Wr,
                 const float* __restrict__ out_w, const float* __restrict__ out_b,
                 float* __restrict__ out)
{
    extern __shared__ char sm[];
    const int tid  = threadIdx.x;
    const int wid  = tid >> 5;
    const int lane = tid & 31;
    const int m0   = wid * 16;        // warp's attention M-row base (0..112)
    const int bb   = wid >> 2;        // batch slot (0/1)
    const int w4   = wid & 3;         // warp index within group

    int*   sIdx = (int*)(sm + OFF_IDX);
    float* sRed = (float*)(sm + OFF_RED);

    if (tid < 128) sIdx[tid] = feat_index[(size_t)blockIdx.x * 128 + tid];
    __syncthreads();

    // ---- gather E -> fp8 [128][144], scaled by SC_E
#pragma unroll
    for (int it = 0; it < 16; it++) {
        int i = tid + it * 256;                 // 128*32 words
        int row = i >> 5, c4 = i & 31;
        float4 v = *(const float4*)(emb + (size_t)sIdx[row] * 128 + c4 * 4);
        *(uint32_t*)(sm + OFF_E + row * 144 + c4 * 4) =
            pack_fp8x4(v.x * SC_E, v.y * SC_E, v.z * SC_E, v.w * SC_E);
    }
    __syncthreads();

    // ---- hoist E A-fragments for this warp's 16 rows (4 kt x 4 regs = 16 regs)
    uint32_t ea[4][4];
#pragma unroll
    for (int kt = 0; kt < 4; kt++)
        lda(ea[kt], sm + OFF_E, 144, m0, kt * 32, lane);

    float oacc = 0.f;

    for (int h = 0; h < Hn; h++) {
        // ================= stage Wk->W0, Wv->W1 (transposed fp8) =================
        stage_w2(sm, Wk, Wv, h, tid);
        __syncthreads();                                   // sync A

        // ================= paired k|v projections, 32 rows/warp =================
        {
            const int mrow = w4 * 32;
            const char* wb = sm + ((wid < 4) ? OFF_W0 : OFF_W1);
            float acc0[32], acc1[32];
#pragma unroll
            for (int i = 0; i < 32; i++) { acc0[i] = 0.f; acc1[i] = 0.f; }
#pragma unroll
            for (int kt = 0; kt < 4; kt++) {
                uint32_t a0[4], a1[4];
                lda(a0, sm + OFF_E, 144, mrow,      kt * 32, lane);
                lda(a1, sm + OFF_E, 144, mrow + 16, kt * 32, lane);
#pragma unroll
                for (int nt = 0; nt < 8; nt++) {
                    const char* bp = wb + (nt * 8 + (lane >> 2)) * 144
                                        + kt * 32 + 4 * (lane & 3);
                    uint32_t b0 = *(const uint32_t*)bp;
                    uint32_t b1 = *(const uint32_t*)(bp + 16);
                    mma16832(&acc0[nt * 4], a0, b0, b1);
                    mma16832(&acc1[nt * 4], a1, b0, b1);
                }
            }
            if (wid < 4) {
                // k -> sK [f][p], scaled x256 (acc/1024 * 256 = acc * 0.25)
                scatter_rows(sm + OFF_K, 80, mrow,      acc0, 0.25f, lane);
                scatter_rows(sm + OFF_K, 80, mrow + 16, acc1, 0.25f, lane);
            } else {
                // v -> sV [p][f] transposed byte scatter, scaled x256
                int g = lane >> 2, q = lane & 3;
#pragma unroll
                for (int mt = 0; mt < 2; mt++) {
                    const float* acc = mt ? acc1 : acc0;
                    int f0 = mrow + mt * 16 + g;
#pragma unroll
                    for (int nt = 0; nt < 8; nt++) {
                        char* c0 = sm + OFF_V + (nt * 8 + 2 * q) * 144;
                        c0[f0]           = fp8b(acc[4 * nt]     * 0.25f);
                        c0[144 + f0]     = fp8b(acc[4 * nt + 1] * 0.25f);
                        c0[f0 + 8]       = fp8b(acc[4 * nt + 2] * 0.25f);
                        c0[144 + f0 + 8] = fp8b(acc[4 * nt + 3] * 0.25f);
                    }
                }
            }
        }
        __syncthreads();                                   // sync B

        // ================= stage Wq->W0, Wr->W1 =================
        stage_w2(sm, Wq, Wr, h, tid);
        __syncthreads();                                   // sync C

        // ================= q projection -> sQA [f][p] fp8 (x256) =================
        {
            float qacc[32];
            run_proj8(qacc, ea, sm + OFF_W0, lane);
            scatter_rows(sm + OFF_QA, 80, m0, qacc, 0.25f, lane);
        }
        __syncwarp();   // own rows only: warp-local visibility suffices

        // ================= scores: S[16x64] = q @ k^T =================
        float sacc[32];
#pragma unroll
        for (int i = 0; i < 32; i++) sacc[i] = 0.f;
#pragma unroll
        for (int kt2 = 0; kt2 < 2; kt2++) {
            uint32_t a[4];
            lda(a, sm + OFF_QA, 80, m0, kt2 * 32, lane);
#pragma unroll
            for (int nt = 0; nt < 8; nt++) {
                const char* bp = sm + OFF_K + (bb * 64 + nt * 8 + (lane >> 2)) * 80
                                    + kt2 * 32 + 4 * (lane & 3);
                mma16832(&sacc[nt * 4], a,
                         *(const uint32_t*)bp, *(const uint32_t*)(bp + 16));
            }
        }

        // ================= softmax over QUERY axis (column-wise, faithful) ======
#pragma unroll
        for (int i = 0; i < 32; i++) sacc[i] = __expf(sacc[i] * SEXP);
        float M[16];
#pragma unroll
        for (int nt = 0; nt < 8; nt++) {
            M[2 * nt]     = sacc[4 * nt]     + sacc[4 * nt + 2];
            M[2 * nt + 1] = sacc[4 * nt + 1] + sacc[4 * nt + 3];
        }
#pragma unroll
        for (int o = 4; o <= 16; o <<= 1)
#pragma unroll
            for (int i = 0; i < 16; i++)
                M[i] += __shfl_xor_sync(0xffffffffu, M[i], o);
        if (lane < 4) {
            char* px = sm + OFF_XS + w4 * 576 + (bb * 72 + lane * 2) * 4;
#pragma unroll
            for (int nt = 0; nt < 8; nt++)
                *(float2*)(px + nt * 32) = make_float2(M[2 * nt], M[2 * nt + 1]);
        }
        __syncthreads();                                   // sync D
        {
            const char* px = sm + OFF_XS + (bb * 72 + (lane & 3) * 2) * 4;
            float inv[16];
#pragma unroll
            for (int nt = 0; nt < 8; nt++) {
                float2 t0 = *(const float2*)(px +         nt * 32);
                float2 t1 = *(const float2*)(px +  576 +  nt * 32);
                float2 t2 = *(const float2*)(px + 1152 +  nt * 32);
                float2 t3 = *(const float2*)(px + 1728 +  nt * 32);
                inv[2 * nt]     = 256.f / (t0.x + t1.x + t2.x + t3.x);
                inv[2 * nt + 1] = 256.f / (t0.y + t1.y + t2.y + t3.y);
            }
            // att -> sQA fp8 (x256), overwrites q (dead; own rows only)
            char* r0 = sm + OFF_QA + (m0 + (lane >> 2)) * 80 + 2 * (lane & 3);
#pragma unroll
            for (int nt = 0; nt < 8; nt++) {
                uint32_t w0 = pack_fp8x2(sacc[4 * nt]     * inv[2 * nt],
                                         sacc[4 * nt + 1] * inv[2 * nt + 1]);
                uint32_t w1 = pack_fp8x2(sacc[4 * nt + 2] * inv[2 * nt],
                                         sacc[4 * nt + 3] * inv[2 * nt + 1]);
                uint32_t h0 = __shfl_down_sync(0xffffffffu, w0, 1);
                uint32_t h1 = __shfl_down_sync(0xffffffffu, w1, 1);
                if (!(lane & 1)) {
                    *(uint32_t*)(r0 + nt * 8)          = w0 | (h0 << 16);
                    *(uint32_t*)(r0 + 8 * 80 + nt * 8) = w1 | (h1 << 16);
                }
            }
        }
        __syncwarp();

        // ================= AV[16x64] = att @ v =================
        float avacc[32];
#pragma unroll
        for (int i = 0; i < 32; i++) avacc[i] = 0.f;
#pragma unroll
        for (int kt2 = 0; kt2 < 2; kt2++) {
            uint32_t a[4];
            lda(a, sm + OFF_QA, 80, m0, kt2 * 32, lane);
#pragma unroll
            for (int nt = 0; nt < 8; nt++) {
                const char* bp = sm + OFF_V + (nt * 8 + (lane >> 2)) * 144
                                    + bb * 64 + kt2 * 32 + 4 * (lane & 3);
                mma16832(&avacc[nt * 4], a,
                         *(const uint32_t*)bp, *(const uint32_t*)(bp + 16));
            }
        }

        // ================= r projection (W1) + fused epilogue =================
        {
            float racc[32];
            run_proj8(racc, ea, sm + OFF_W1, lane);

            int frow = (m0 & 63) + (lane >> 2);
            const float* ow = out_w + (size_t)h * 64 + 2 * (lane & 3);
#pragma unroll
            for (int nt = 0; nt < 8; nt++) {
                float2 w0 = *(const float2*)(ow + (size_t)frow * 512 + nt * 8);
                float2 w1 = *(const float2*)(ow + (size_t)(frow + 8) * 512 + nt * 8);
                float v0 = avacc[4 * nt]     * IS_AV + racc[4 * nt]     * IS_R;
                float v1 = avacc[4 * nt + 1] * IS_AV + racc[4 * nt + 1] * IS_R;
                float v2 = avacc[4 * nt + 2] * IS_AV + racc[4 * nt + 2] * IS_R;
                float v3 = avacc[4 * nt + 3] * IS_AV + racc[4 * nt + 3] * IS_R;
                oacc += fmaxf(v0, 0.f) * w0.x;
                oacc += fmaxf(v1, 0.f) * w0.y;
                oacc += fmaxf(v2, 0.f) * w1.x;
                oacc += fmaxf(v3, 0.f) * w1.y;
            }
        }
        __syncthreads();                                   // sync E
    }

    // ---- reduce: warps 0-3 -> batch0, 4-7 -> batch1
#pragma unroll
    for (int o = 16; o; o >>= 1) oacc += __shfl_xor_sync(0xffffffffu, oacc, o);
    if (lane == 0) sRed[wid] = oacc;
    __syncthreads();
    if (tid == 0) {
        float s = sRed[0] + sRed[1] + sRed[2] + sRed[3] + out_b[0];
        out[blockIdx.x * 2] = 1.f / (1.f + expf(-s));
    }
    if (tid == 1) {
        float s = sRed[4] + sRed[5] + sRed[6] + sRed[7] + out_b[0];
        out[blockIdx.x * 2 + 1] = 1.f / (1.f + expf(-s));
    }
}

extern "C" void kernel_launch(void* const* d_in, const int* in_sizes, int n_in,
                              void* d_out, int out_size)
{
    cudaFuncSetAttribute(autoint_fp8, cudaFuncAttributeMaxDynamicSharedMemorySize, SMEM_BYTES);
    autoint_fp8<<<Bn / 2, 256, SMEM_BYTES>>>(
        (const int*)d_in[0], (const float*)d_in[1],
        (const float*)d_in[2], (const float*)d_in[3],
        (const float*)d_in[4], (const float*)d_in[5],
        (const float*)d_in[6], (const float*)d_in[7], (float*)d_out);
}

// round 10
// speedup vs baseline: 1.9806x; 1.9806x over previous
#include <cuda_runtime.h>
#include <cuda_bf16.h>
#include <cstdint>
#include <math.h>

#define Bn 2048
#define Hn 8

namespace {
// SMEM byte offsets (16B-aligned rows; padded strides, no swizzle)
constexpr int OFF_IDX = 0;                    // 128 int
constexpr int OFF_RED = 512;                  // 8 float
constexpr int OFF_XS  = 576;                  // fp32 [4][144] sum-exchange
constexpr int OFF_E   = 3072;                 // bf16 [128 f][128 k] stride 272B
constexpr int OFF_W0  = OFF_E  + 128 * 272;   // bf16 [64 n][128 k] stride 272B
constexpr int OFF_W1  = OFF_W0 + 64 * 272;    // bf16 [64 n][128 k]
constexpr int OFF_K   = OFF_W1 + 64 * 272;    // bf16 [128 f][64 p] stride 144B
constexpr int OFF_V   = OFF_K  + 128 * 144;   // bf16 [128 f][64 p] stride 144B
constexpr int SMEM_BYTES = OFF_V + 128 * 144; // 109568 B -> 2 CTAs/SM
}

// Pre-transposed bf16 weights: [m][h][n][k], m: 0=Wk 1=Wv 2=Wq 3=Wr
__device__ __nv_bfloat16 gWt[4][Hn][64][128];

__global__ void prep_w(const float* __restrict__ Wk, const float* __restrict__ Wv,
                       const float* __restrict__ Wq, const float* __restrict__ Wr)
{
    const float* Ws[4] = {Wk, Wv, Wq, Wr};
    const int m = blockIdx.x >> 3;
    const int h = blockIdx.x & 7;
    const float* W = Ws[m];
    const int t = threadIdx.x;
    const int n = t & 63, q = t >> 6;           // q: 0..3
#pragma unroll
    for (int i = 0; i < 8; i++) {
        int k = q * 32 + i * 4;
        __nv_bfloat16 tmp[4];
#pragma unroll
        for (int j = 0; j < 4; j++)             // reads coalesced along n
            tmp[j] = __float2bfloat16(W[(size_t)(k + j) * 512 + h * 64 + n]);
        *(uint2*)&gWt[m][h][n][k] = *(const uint2*)tmp;
    }
}

__device__ __forceinline__ uint32_t smem_u32(const void* p) {
    uint32_t a;
    asm("{ .reg .u64 t; cvta.to.shared.u64 t, %1; cvt.u32.u64 %0, t; }" : "=r"(a) : "l"(p));
    return a;
}
__device__ __forceinline__ uint32_t pack_bf16x2(float lo, float hi) {
    uint32_t r;
    asm("cvt.rn.bf16x2.f32 %0, %1, %2;" : "=r"(r) : "f"(hi), "f"(lo));
    return r;
}
__device__ __forceinline__ void ldsm4(uint32_t* r, uint32_t addr) {
    asm volatile("ldmatrix.sync.aligned.m8n8.x4.shared.b16 {%0,%1,%2,%3}, [%4];"
                 : "=r"(r[0]), "=r"(r[1]), "=r"(r[2]), "=r"(r[3]) : "r"(addr));
}
__device__ __forceinline__ void ldsm4t(uint32_t* r, uint32_t addr) {
    asm volatile("ldmatrix.sync.aligned.m8n8.x4.trans.shared.b16 {%0,%1,%2,%3}, [%4];"
                 : "=r"(r[0]), "=r"(r[1]), "=r"(r[2]), "=r"(r[3]) : "r"(addr));
}
__device__ __forceinline__ void mma16816(float* c, const uint32_t* a, uint32_t b0, uint32_t b1) {
    asm volatile(
        "mma.sync.aligned.m16n8k16.row.col.f32.bf16.bf16.f32 "
        "{%0,%1,%2,%3}, {%4,%5,%6,%7}, {%8,%9}, {%0,%1,%2,%3};"
        : "+f"(c[0]), "+f"(c[1]), "+f"(c[2]), "+f"(c[3])
        : "r"(a[0]), "r"(a[1]), "r"(a[2]), "r"(a[3]), "r"(b0), "r"(b1));
}

// B-fragment address for [n][k] bf16 tiles, stride 272B (non-trans ldsm4).
__device__ __forceinline__ uint32_t baddr(uint32_t base, int nt16, int kt16, int lane) {
    return base + (nt16 + (lane >> 4) * 8 + (lane & 7)) * 272
                + (kt16 + ((lane >> 3) & 1) * 8) * 2;
}

// C[16x64] = E[16x128] @ W[128x64]; A from hoisted E frags, B non-trans from [n][k]
__device__ __forceinline__ void run_proj(float acc[32], const uint32_t ea[8][4],
                                         uint32_t wbase, int lane) {
#pragma unroll
    for (int i = 0; i < 32; i++) acc[i] = 0.f;
#pragma unroll
    for (int kt = 0; kt < 8; kt++) {
#pragma unroll
        for (int nt2 = 0; nt2 < 4; nt2++) {
            uint32_t b[4];
            ldsm4(b, baddr(wbase, nt2 * 16, kt * 16, lane));
            mma16816(&acc[nt2 * 8],     ea[kt], b[0], b[1]);
            mma16816(&acc[nt2 * 8 + 4], ea[kt], b[2], b[3]);
        }
    }
}

// stage two pre-converted W tiles (pair 0: k,v ; pair 1: q,r) as uint4 copies
__device__ __forceinline__ void stage_pair(char* sm, int pair, int h, int tid) {
#pragma unroll
    for (int it = 0; it < 8; it++) {
        int i = tid + it * 256;                 // 2048 uint4 total
        int m2 = i >> 10, j = i & 1023;         // tile, element
        int row = j >> 4, c = j & 15;
        uint4 v = ((const uint4*)&gWt[pair * 2 + m2][h][0][0])[j];
        *(uint4*)(sm + (m2 ? OFF_W1 : OFF_W0) + row * 272 + c * 16) = v;
    }
}

__global__ __launch_bounds__(256, 2)
void autoint_mma(const int*   __restrict__ feat_index,
                 const float* __restrict__ emb,
                 const float* __restrict__ out_w, const float* __restrict__ out_b,
                 float* __restrict__ out)
{
    extern __shared__ char sm[];
    const uint32_t smb = smem_u32(sm);
    const int tid  = threadIdx.x;
    const int wid  = tid >> 5;
    const int lane = tid & 31;
    const int m0   = wid * 16;        // warp's attention M-row base (0..112)
    const int bb   = wid >> 2;        // batch slot (0/1)
    const int w4   = wid & 3;         // warp index within batch

    int*   sIdx = (int*)(sm + OFF_IDX);
    float* sRed = (float*)(sm + OFF_RED);

    if (tid < 128) sIdx[tid] = feat_index[(size_t)blockIdx.x * 128 + tid];
    __syncthreads();

    // ---- gather E -> bf16 [128][136]
#pragma unroll
    for (int it = 0; it < 32; it++) {
        int i = tid + it * 256;
        int row = i >> 6, c2 = i & 63;
        float2 v = *(const float2*)(emb + (size_t)sIdx[row] * 128 + 2 * c2);
        *(uint32_t*)(sm + OFF_E + row * 272 + c2 * 4) = pack_bf16x2(v.x, v.y);
    }
    __syncthreads();

    // ---- hoist E A-fragments for this warp's 16 attention rows
    uint32_t ea[8][4];
#pragma unroll
    for (int kt = 0; kt < 8; kt++)
        ldsm4(ea[kt], smb + OFF_E + (m0 + (lane & 15)) * 272
                          + (kt * 16 + (lane >> 4) * 8) * 2);

    float oacc = 0.f;

    for (int h = 0; h < Hn; h++) {
        // ================= stage Wk->W0, Wv->W1 =================
        stage_pair(sm, 0, h, tid);
        __syncthreads();                                   // sync A

        // ================= paired k|v projections, 32 rows/warp =================
        // warps 0-3: k from W0 -> sK ; warps 4-7: v from W1 -> sV
        {
            const int mrow = w4 * 32;
            const uint32_t wb = smb + ((wid < 4) ? OFF_W0 : OFF_W1);
            char* po = sm + ((wid < 4) ? OFF_K : OFF_V);
            float acc0[32], acc1[32];
#pragma unroll
            for (int i = 0; i < 32; i++) { acc0[i] = 0.f; acc1[i] = 0.f; }
#pragma unroll
            for (int kt = 0; kt < 8; kt++) {
                uint32_t a0[4], a1[4];
                uint32_t ab = smb + OFF_E + (mrow + (lane & 15)) * 272
                                  + (kt * 16 + (lane >> 4) * 8) * 2;
                ldsm4(a0, ab);
                ldsm4(a1, ab + 16 * 272);
#pragma unroll
                for (int nt2 = 0; nt2 < 4; nt2++) {
                    uint32_t b[4];
                    ldsm4(b, baddr(wb, nt2 * 16, kt * 16, lane));
                    mma16816(&acc0[nt2 * 8],     a0, b[0], b[1]);
                    mma16816(&acc0[nt2 * 8 + 4], a0, b[2], b[3]);
                    mma16816(&acc1[nt2 * 8],     a1, b[0], b[1]);
                    mma16816(&acc1[nt2 * 8 + 4], a1, b[2], b[3]);
                }
            }
#pragma unroll
            for (int mt = 0; mt < 2; mt++) {
                const float* acc = mt ? acc1 : acc0;
                char* p0 = po + (mrow + mt * 16 + (lane >> 2)) * 144 + (lane & 3) * 4;
#pragma unroll
                for (int j = 0; j < 8; j++) {
                    *(uint32_t*)(p0 + j * 16)           = pack_bf16x2(acc[4*j],   acc[4*j+1]);
                    *(uint32_t*)(p0 + 8 * 144 + j * 16) = pack_bf16x2(acc[4*j+2], acc[4*j+3]);
                }
            }
        }
        __syncthreads();                                   // sync B (sK/sV ready, W free)

        // ================= stage Wq->W0, Wr->W1 =================
        stage_pair(sm, 1, h, tid);
        __syncthreads();                                   // sync C

        // ================= q projection -> A-fragments =================
        uint32_t qf[4][4];
        {
            float acc[32];
            run_proj(acc, ea, smb + OFF_W0, lane);
#pragma unroll
            for (int kt = 0; kt < 4; kt++) {
                qf[kt][0] = pack_bf16x2(acc[8*kt],   acc[8*kt+1]);
                qf[kt][1] = pack_bf16x2(acc[8*kt+2], acc[8*kt+3]);
                qf[kt][2] = pack_bf16x2(acc[8*kt+4], acc[8*kt+5]);
                qf[kt][3] = pack_bf16x2(acc[8*kt+6], acc[8*kt+7]);
            }
        }

        // ================= scores: S[16x64] = q @ k^T (in registers) ==========
        float sacc[32];
#pragma unroll
        for (int i = 0; i < 32; i++) sacc[i] = 0.f;
#pragma unroll
        for (int kt = 0; kt < 4; kt++) {
#pragma unroll
            for (int nt2 = 0; nt2 < 4; nt2++) {
                uint32_t b[4];   // non-trans: B from sK[f_k][p] stride 144
                ldsm4(b, smb + OFF_K
                         + (bb * 64 + nt2 * 16 + (lane >> 4) * 8 + (lane & 7)) * 144
                         + (kt * 16 + ((lane >> 3) & 1) * 8) * 2);
                mma16816(&sacc[nt2 * 8],     qf[kt], b[0], b[1]);
                mma16816(&sacc[nt2 * 8 + 4], qf[kt], b[2], b[3]);
            }
        }

        // ================= softmax over QUERY axis (no max-shift: scores O(0.3))
#pragma unroll
        for (int i = 0; i < 32; i++) sacc[i] = __expf(sacc[i]);
        float M[16];
#pragma unroll
        for (int j = 0; j < 8; j++) {
            M[2*j]   = sacc[4*j]   + sacc[4*j+2];
            M[2*j+1] = sacc[4*j+1] + sacc[4*j+3];
        }
#pragma unroll
        for (int o = 4; o <= 16; o <<= 1)
#pragma unroll
            for (int i = 0; i < 16; i++)
                M[i] += __shfl_xor_sync(0xffffffffu, M[i], o);
        if (lane < 4) {
            char* px = sm + OFF_XS + w4 * 576 + (bb * 72 + lane * 2) * 4;
#pragma unroll
            for (int j = 0; j < 8; j++)
                *(float2*)(px + j * 32) = make_float2(M[2*j], M[2*j+1]);
        }
        __syncthreads();                                   // sync D
        uint32_t af[4][4];
        {
            const char* px = sm + OFF_XS + (bb * 72 + (lane & 3) * 2) * 4;
            float inv[16];
#pragma unroll
            for (int j = 0; j < 8; j++) {
                float2 t0 = *(const float2*)(px +         j * 32);
                float2 t1 = *(const float2*)(px +  576 +  j * 32);
                float2 t2 = *(const float2*)(px + 1152 +  j * 32);
                float2 t3 = *(const float2*)(px + 1728 +  j * 32);
                inv[2*j]   = 1.f / (t0.x + t1.x + t2.x + t3.x);
                inv[2*j+1] = 1.f / (t0.y + t1.y + t2.y + t3.y);
            }
            // att -> A-fragments directly (C layout == A layout)
#pragma unroll
            for (int kt = 0; kt < 4; kt++) {
                af[kt][0] = pack_bf16x2(sacc[8*kt]   * inv[4*kt],   sacc[8*kt+1] * inv[4*kt+1]);
                af[kt][1] = pack_bf16x2(sacc[8*kt+2] * inv[4*kt],   sacc[8*kt+3] * inv[4*kt+1]);
                af[kt][2] = pack_bf16x2(sacc[8*kt+4] * inv[4*kt+2], sacc[8*kt+5] * inv[4*kt+3]);
                af[kt][3] = pack_bf16x2(sacc[8*kt+6] * inv[4*kt+2], sacc[8*kt+7] * inv[4*kt+3]);
            }
        }

        // ================= AV[16x64] = att @ v =================
        float avacc[32];
#pragma unroll
        for (int i = 0; i < 32; i++) avacc[i] = 0.f;
#pragma unroll
        for (int kt = 0; kt < 4; kt++) {
#pragma unroll
            for (int nt2 = 0; nt2 < 4; nt2++) {
                uint32_t b[4];   // trans: B from sV[f_k][p] stride 144
                ldsm4t(b, smb + OFF_V
                          + (bb * 64 + kt * 16 + (lane & 15)) * 144
                          + (nt2 * 16 + (lane >> 4) * 8) * 2);
                mma16816(&avacc[nt2 * 8],     af[kt], b[0], b[1]);
                mma16816(&avacc[nt2 * 8 + 4], af[kt], b[2], b[3]);
            }
        }

        // ================= r projection (W1, staged at sync C) + epilogue ======
        {
            float acc[32];
            run_proj(acc, ea, smb + OFF_W1, lane);

            int frow = (m0 & 63) + (lane >> 2);            // local feature row
            const float* ow = out_w + (size_t)h * 64 + 2 * (lane & 3);
#pragma unroll
            for (int j = 0; j < 8; j++) {
                float2 w0 = *(const float2*)(ow + (size_t)frow * 512 + j * 8);
                float2 w1 = *(const float2*)(ow + (size_t)(frow + 8) * 512 + j * 8);
                float v0 = avacc[4*j]   + acc[4*j];
                float v1 = avacc[4*j+1] + acc[4*j+1];
                float v2 = avacc[4*j+2] + acc[4*j+2];
                float v3 = avacc[4*j+3] + acc[4*j+3];
                if (v0 > 0.f) oacc += v0 * w0.x;
                if (v1 > 0.f) oacc += v1 * w0.y;
                if (v2 > 0.f) oacc += v2 * w1.x;
                if (v3 > 0.f) oacc += v3 * w1.y;
            }
        }
        __syncthreads();                                   // sync E (protect all tiles)
    }

    // ---- reduce: warps 0-3 -> batch0, 4-7 -> batch1
#pragma unroll
    for (int o = 16; o; o >>= 1) oacc += __shfl_xor_sync(0xffffffffu, oacc, o);
    if (lane == 0) sRed[wid] = oacc;
    __syncthreads();
    if (tid == 0) {
        float s = sRed[0] + sRed[1] + sRed[2] + sRed[3] + out_b[0];
        out[blockIdx.x * 2] = 1.f / (1.f + expf(-s));
    }
    if (tid == 1) {
        float s = sRed[4] + sRed[5] + sRed[6] + sRed[7] + out_b[0];
        out[blockIdx.x * 2 + 1] = 1.f / (1.f + expf(-s));
    }
}

extern "C" void kernel_launch(void* const* d_in, const int* in_sizes, int n_in,
                              void* d_out, int out_size)
{
    const float* Wq = (const float*)d_in[2];
    const float* Wk = (const float*)d_in[3];
    const float* Wv = (const float*)d_in[4];
    const float* Wr = (const float*)d_in[5];

    cudaFuncSetAttribute(autoint_mma, cudaFuncAttributeMaxDynamicSharedMemorySize, SMEM_BYTES);

    prep_w<<<32, 256>>>(Wk, Wv, Wq, Wr);
    autoint_mma<<<Bn / 2, 256, SMEM_BYTES>>>(
        (const int*)d_in[0], (const float*)d_in[1],
        (const float*)d_in[6], (const float*)d_in[7], (float*)d_out);
}

// round 11
// speedup vs baseline: 2.1191x; 1.0699x over previous
#include <cuda_runtime.h>
#include <cuda_bf16.h>
#include <cstdint>
#include <math.h>

#define Bn 2048
#define Hn 8

namespace {
// SMEM byte offsets (16B-aligned rows; padded strides, no swizzle)
constexpr int OFF_IDX = 0;                    // 128 int
constexpr int OFF_RED = 512;                  // 8 float
constexpr int OFF_XS  = 576;                  // fp32 [4][144] sum-exchange
constexpr int OFF_E   = 3072;                 // bf16 [128 f][128 k] stride 272B
constexpr int OFF_W0  = OFF_E  + 128 * 272;   // bf16 [64 n][128 k] stride 272B
constexpr int OFF_W1  = OFF_W0 + 64 * 272;    // bf16 [64 n][128 k]
constexpr int OFF_K   = OFF_W1 + 64 * 272;    // bf16 [128 f][64 p] stride 144B
constexpr int OFF_V   = OFF_K  + 128 * 144;   // bf16 [128 f][64 p] stride 144B
constexpr int SMEM_BYTES = OFF_V + 128 * 144; // 109568 B -> 2 CTAs/SM
}

// Pre-transposed bf16 weights: [m][h][n][k], m: 0=Wk 1=Wv 2=Wq 3=Wr
__device__ __nv_bfloat16 gWt[4][Hn][64][128];
// Pre-packed out_w in per-thread fragment order: [h][w4][j][lane] =
// {(frow,2q),(frow,2q+1),(frow+8,2q),(frow+8,2q+1)}, frow=w4*16+(lane>>2), q=lane&3
__device__ float4 gOwP[Hn][4][8][32];

__global__ void prep_w(const float* __restrict__ Wk, const float* __restrict__ Wv,
                       const float* __restrict__ Wq, const float* __restrict__ Wr)
{
    const float* Ws[4] = {Wk, Wv, Wq, Wr};
    const int m = blockIdx.x >> 3;
    const int h = blockIdx.x & 7;
    const float* W = Ws[m];
    const int t = threadIdx.x;
    const int n = t & 63, q = t >> 6;           // q: 0..3
#pragma unroll
    for (int i = 0; i < 8; i++) {
        int k = q * 32 + i * 4;
        __nv_bfloat16 tmp[4];
#pragma unroll
        for (int j = 0; j < 4; j++)             // reads coalesced along n
            tmp[j] = __float2bfloat16(W[(size_t)(k + j) * 512 + h * 64 + n]);
        *(uint2*)&gWt[m][h][n][k] = *(const uint2*)tmp;
    }
}

__global__ void prep_ow(const float* __restrict__ ow) {
    int id = blockIdx.x * 256 + threadIdx.x;    // 8192 total
    int lane = id & 31, j = (id >> 5) & 7, w4 = (id >> 8) & 3, h = id >> 10;
    int frow = w4 * 16 + (lane >> 2), q = lane & 3;
    const float* p0 = ow + (size_t)frow * 512 + h * 64 + j * 8 + 2 * q;
    const float* p1 = ow + (size_t)(frow + 8) * 512 + h * 64 + j * 8 + 2 * q;
    gOwP[h][w4][j][lane] = make_float4(p0[0], p0[1], p1[0], p1[1]);
}

__device__ __forceinline__ uint32_t smem_u32(const void* p) {
    uint32_t a;
    asm("{ .reg .u64 t; cvta.to.shared.u64 t, %1; cvt.u32.u64 %0, t; }" : "=r"(a) : "l"(p));
    return a;
}
__device__ __forceinline__ uint32_t pack_bf16x2(float lo, float hi) {
    uint32_t r;
    asm("cvt.rn.bf16x2.f32 %0, %1, %2;" : "=r"(r) : "f"(hi), "f"(lo));
    return r;
}
__device__ __forceinline__ void ldsm4(uint32_t* r, uint32_t addr) {
    asm volatile("ldmatrix.sync.aligned.m8n8.x4.shared.b16 {%0,%1,%2,%3}, [%4];"
                 : "=r"(r[0]), "=r"(r[1]), "=r"(r[2]), "=r"(r[3]) : "r"(addr));
}
__device__ __forceinline__ void ldsm4t(uint32_t* r, uint32_t addr) {
    asm volatile("ldmatrix.sync.aligned.m8n8.x4.trans.shared.b16 {%0,%1,%2,%3}, [%4];"
                 : "=r"(r[0]), "=r"(r[1]), "=r"(r[2]), "=r"(r[3]) : "r"(addr));
}
__device__ __forceinline__ void mma16816(float* c, const uint32_t* a, uint32_t b0, uint32_t b1) {
    asm volatile(
        "mma.sync.aligned.m16n8k16.row.col.f32.bf16.bf16.f32 "
        "{%0,%1,%2,%3}, {%4,%5,%6,%7}, {%8,%9}, {%0,%1,%2,%3};"
        : "+f"(c[0]), "+f"(c[1]), "+f"(c[2]), "+f"(c[3])
        : "r"(a[0]), "r"(a[1]), "r"(a[2]), "r"(a[3]), "r"(b0), "r"(b1));
}

// B-fragment address for [n][k] bf16 tiles, stride 272B (non-trans ldsm4).
__device__ __forceinline__ uint32_t baddr(uint32_t base, int nt16, int kt16, int lane) {
    return base + (nt16 + (lane >> 4) * 8 + (lane & 7)) * 272
                + (kt16 + ((lane >> 3) & 1) * 8) * 2;
}

// C[16x64] = E[16x128] @ W[128x64]; A from hoisted E frags, B non-trans from [n][k]
__device__ __forceinline__ void run_proj(float acc[32], const uint32_t ea[8][4],
                                         uint32_t wbase, int lane) {
#pragma unroll
    for (int i = 0; i < 32; i++) acc[i] = 0.f;
#pragma unroll
    for (int kt = 0; kt < 8; kt++) {
#pragma unroll
        for (int nt2 = 0; nt2 < 4; nt2++) {
            uint32_t b[4];
            ldsm4(b, baddr(wbase, nt2 * 16, kt * 16, lane));
            mma16816(&acc[nt2 * 8],     ea[kt], b[0], b[1]);
            mma16816(&acc[nt2 * 8 + 4], ea[kt], b[2], b[3]);
        }
    }
}

// async-stage two pre-converted W tiles (pair 0: k,v ; pair 1: q,r) via cp.async
__device__ __forceinline__ void stage_pair_async(uint32_t smb, int pair, int h, int tid) {
#pragma unroll
    for (int it = 0; it < 8; it++) {
        int i = tid + it * 256;                 // 2048 uint4 total
        int m2 = i >> 10, j = i & 1023;         // tile, element
        int row = j >> 4, c = j & 15;
        uint32_t dst = smb + (m2 ? OFF_W1 : OFF_W0) + row * 272 + c * 16;
        const void* src = &((const uint4*)&gWt[pair * 2 + m2][h][0][0])[j];
        asm volatile("cp.async.cg.shared.global [%0], [%1], 16;"
                     :: "r"(dst), "l"(src) : "memory");
    }
    asm volatile("cp.async.commit_group;" ::: "memory");
}
__device__ __forceinline__ void cp_wait_all() {
    asm volatile("cp.async.wait_group 0;" ::: "memory");
}

__global__ __launch_bounds__(256, 2)
void autoint_mma(const int*   __restrict__ feat_index,
                 const float* __restrict__ emb,
                 const float* __restrict__ out_b,
                 float* __restrict__ out)
{
    extern __shared__ char sm[];
    const uint32_t smb = smem_u32(sm);
    const int tid  = threadIdx.x;
    const int wid  = tid >> 5;
    const int lane = tid & 31;
    const int m0   = wid * 16;        // warp's attention M-row base (0..112)
    const int bb   = wid >> 2;        // batch slot (0/1)
    const int w4   = wid & 3;         // warp index within batch

    int*   sIdx = (int*)(sm + OFF_IDX);
    float* sRed = (float*)(sm + OFF_RED);

    // ---- prefetch kv(0) while we gather E
    stage_pair_async(smb, 0, 0, tid);

    if (tid < 128) sIdx[tid] = feat_index[(size_t)blockIdx.x * 128 + tid];
    __syncthreads();

    // ---- gather E -> bf16 [128][136]
#pragma unroll
    for (int it = 0; it < 32; it++) {
        int i = tid + it * 256;
        int row = i >> 6, c2 = i & 63;
        float2 v = *(const float2*)(emb + (size_t)sIdx[row] * 128 + 2 * c2);
        *(uint32_t*)(sm + OFF_E + row * 272 + c2 * 4) = pack_bf16x2(v.x, v.y);
    }
    __syncthreads();

    // ---- hoist E A-fragments for this warp's 16 attention rows
    uint32_t ea[8][4];
#pragma unroll
    for (int kt = 0; kt < 8; kt++)
        ldsm4(ea[kt], smb + OFF_E + (m0 + (lane & 15)) * 272
                          + (kt * 16 + (lane >> 4) * 8) * 2);

    float oacc = 0.f;

    for (int h = 0; h < Hn; h++) {
        cp_wait_all();
        __syncthreads();                                   // sync A: Wk/Wv ready

        // ================= paired k|v projections, 32 rows/warp =================
        // warps 0-3: k from W0 -> sK ; warps 4-7: v from W1 -> sV
        {
            const int mrow = w4 * 32;
            const uint32_t wb = smb + ((wid < 4) ? OFF_W0 : OFF_W1);
            char* po = sm + ((wid < 4) ? OFF_K : OFF_V);
            float acc0[32], acc1[32];
#pragma unroll
            for (int i = 0; i < 32; i++) { acc0[i] = 0.f; acc1[i] = 0.f; }
#pragma unroll
            for (int kt = 0; kt < 8; kt++) {
                uint32_t a0[4], a1[4];
                uint32_t ab = smb + OFF_E + (mrow + (lane & 15)) * 272
                                  + (kt * 16 + (lane >> 4) * 8) * 2;
                ldsm4(a0, ab);
                ldsm4(a1, ab + 16 * 272);
#pragma unroll
                for (int nt2 = 0; nt2 < 4; nt2++) {
                    uint32_t b[4];
                    ldsm4(b, baddr(wb, nt2 * 16, kt * 16, lane));
                    mma16816(&acc0[nt2 * 8],     a0, b[0], b[1]);
                    mma16816(&acc0[nt2 * 8 + 4], a0, b[2], b[3]);
                    mma16816(&acc1[nt2 * 8],     a1, b[0], b[1]);
                    mma16816(&acc1[nt2 * 8 + 4], a1, b[2], b[3]);
                }
            }
            __syncthreads();               // sync B: all warps done reading W0/W1

            // overlap: issue q/r copy, then store kv fragments while it flies
            stage_pair_async(smb, 1, h, tid);
#pragma unroll
            for (int mt = 0; mt < 2; mt++) {
                const float* acc = mt ? acc1 : acc0;
                char* p0 = po + (mrow + mt * 16 + (lane >> 2)) * 144 + (lane & 3) * 4;
#pragma unroll
                for (int j = 0; j < 8; j++) {
                    *(uint32_t*)(p0 + j * 16)           = pack_bf16x2(acc[4*j],   acc[4*j+1]);
                    *(uint32_t*)(p0 + 8 * 144 + j * 16) = pack_bf16x2(acc[4*j+2], acc[4*j+3]);
                }
            }
        }
        cp_wait_all();
        __syncthreads();                                   // sync C: Wq/Wr + sK/sV ready

        // ================= q projection -> A-fragments =================
        uint32_t qf[4][4];
        {
            float acc[32];
            run_proj(acc, ea, smb + OFF_W0, lane);
#pragma unroll
            for (int kt = 0; kt < 4; kt++) {
                qf[kt][0] = pack_bf16x2(acc[8*kt],   acc[8*kt+1]);
                qf[kt][1] = pack_bf16x2(acc[8*kt+2], acc[8*kt+3]);
                qf[kt][2] = pack_bf16x2(acc[8*kt+4], acc[8*kt+5]);
                qf[kt][3] = pack_bf16x2(acc[8*kt+6], acc[8*kt+7]);
            }
        }

        // ================= scores: S[16x64] = q @ k^T (in registers) ==========
        float sacc[32];
#pragma unroll
        for (int i = 0; i < 32; i++) sacc[i] = 0.f;
#pragma unroll
        for (int kt = 0; kt < 4; kt++) {
#pragma unroll
            for (int nt2 = 0; nt2 < 4; nt2++) {
                uint32_t b[4];   // non-trans: B from sK[f_k][p] stride 144
                ldsm4(b, smb + OFF_K
                         + (bb * 64 + nt2 * 16 + (lane >> 4) * 8 + (lane & 7)) * 144
                         + (kt * 16 + ((lane >> 3) & 1) * 8) * 2);
                mma16816(&sacc[nt2 * 8],     qf[kt], b[0], b[1]);
                mma16816(&sacc[nt2 * 8 + 4], qf[kt], b[2], b[3]);
            }
        }

        // ================= softmax over QUERY axis (no max-shift: scores O(0.3))
#pragma unroll
        for (int i = 0; i < 32; i++) sacc[i] = __expf(sacc[i]);
        float M[16];
#pragma unroll
        for (int j = 0; j < 8; j++) {
            M[2*j]   = sacc[4*j]   + sacc[4*j+2];
            M[2*j+1] = sacc[4*j+1] + sacc[4*j+3];
        }
#pragma unroll
        for (int o = 4; o <= 16; o <<= 1)
#pragma unroll
            for (int i = 0; i < 16; i++)
                M[i] += __shfl_xor_sync(0xffffffffu, M[i], o);
        if (lane < 4) {
            char* px = sm + OFF_XS + w4 * 576 + (bb * 72 + lane * 2) * 4;
#pragma unroll
            for (int j = 0; j < 8; j++)
                *(float2*)(px + j * 32) = make_float2(M[2*j], M[2*j+1]);
        }
        __syncthreads();                                   // sync D
        uint32_t af[4][4];
        {
            const char* px = sm + OFF_XS + (bb * 72 + (lane & 3) * 2) * 4;
            float inv[16];
#pragma unroll
            for (int j = 0; j < 8; j++) {
                float2 t0 = *(const float2*)(px +         j * 32);
                float2 t1 = *(const float2*)(px +  576 +  j * 32);
                float2 t2 = *(const float2*)(px + 1152 +  j * 32);
                float2 t3 = *(const float2*)(px + 1728 +  j * 32);
                inv[2*j]   = 1.f / (t0.x + t1.x + t2.x + t3.x);
                inv[2*j+1] = 1.f / (t0.y + t1.y + t2.y + t3.y);
            }
            // att -> A-fragments directly (C layout == A layout)
#pragma unroll
            for (int kt = 0; kt < 4; kt++) {
                af[kt][0] = pack_bf16x2(sacc[8*kt]   * inv[4*kt],   sacc[8*kt+1] * inv[4*kt+1]);
                af[kt][1] = pack_bf16x2(sacc[8*kt+2] * inv[4*kt],   sacc[8*kt+3] * inv[4*kt+1]);
                af[kt][2] = pack_bf16x2(sacc[8*kt+4] * inv[4*kt+2], sacc[8*kt+5] * inv[4*kt+3]);
                af[kt][3] = pack_bf16x2(sacc[8*kt+6] * inv[4*kt+2], sacc[8*kt+7] * inv[4*kt+3]);
            }
        }

        // ================= AV[16x64] = att @ v =================
        float avacc[32];
#pragma unroll
        for (int i = 0; i < 32; i++) avacc[i] = 0.f;
#pragma unroll
        for (int kt = 0; kt < 4; kt++) {
#pragma unroll
            for (int nt2 = 0; nt2 < 4; nt2++) {
                uint32_t b[4];   // trans: B from sV[f_k][p] stride 144
                ldsm4t(b, smb + OFF_V
                          + (bb * 64 + kt * 16 + (lane & 15)) * 144
                          + (nt2 * 16 + (lane >> 4) * 8) * 2);
                mma16816(&avacc[nt2 * 8],     af[kt], b[0], b[1]);
                mma16816(&avacc[nt2 * 8 + 4], af[kt], b[2], b[3]);
            }
        }

        // ================= r projection (W1) =================
        float racc[32];
        run_proj(racc, ea, smb + OFF_W1, lane);
        __syncthreads();                   // sync E: all done reading W1 / tiles

        // overlap: prefetch next head's kv while we run the epilogue
        if (h + 1 < Hn) stage_pair_async(smb, 0, h + 1, tid);

        // ================= fused epilogue (pre-packed out_w) =================
        {
            const float4* owp = &gOwP[h][w4][0][lane];
#pragma unroll
            for (int j = 0; j < 8; j++) {
                float4 w = owp[j * 32];
                float v0 = avacc[4*j]   + racc[4*j];
                float v1 = avacc[4*j+1] + racc[4*j+1];
                float v2 = avacc[4*j+2] + racc[4*j+2];
                float v3 = avacc[4*j+3] + racc[4*j+3];
                if (v0 > 0.f) oacc += v0 * w.x;
                if (v1 > 0.f) oacc += v1 * w.y;
                if (v2 > 0.f) oacc += v2 * w.z;
                if (v3 > 0.f) oacc += v3 * w.w;
            }
        }
    }

    // ---- reduce: warps 0-3 -> batch0, 4-7 -> batch1
#pragma unroll
    for (int o = 16; o; o >>= 1) oacc += __shfl_xor_sync(0xffffffffu, oacc, o);
    if (lane == 0) sRed[wid] = oacc;
    __syncthreads();
    if (tid == 0) {
        float s = sRed[0] + sRed[1] + sRed[2] + sRed[3] + out_b[0];
        out[blockIdx.x * 2] = 1.f / (1.f + expf(-s));
    }
    if (tid == 1) {
        float s = sRed[4] + sRed[5] + sRed[6] + sRed[7] + out_b[0];
        out[blockIdx.x * 2 + 1] = 1.f / (1.f + expf(-s));
    }
}

extern "C" void kernel_launch(void* const* d_in, const int* in_sizes, int n_in,
                              void* d_out, int out_size)
{
    const float* Wq = (const float*)d_in[2];
    const float* Wk = (const float*)d_in[3];
    const float* Wv = (const float*)d_in[4];
    const float* Wr = (const float*)d_in[5];

    cudaFuncSetAttribute(autoint_mma, cudaFuncAttributeMaxDynamicSharedMemorySize, SMEM_BYTES);

    prep_w<<<32, 256>>>(Wk, Wv, Wq, Wr);
    prep_ow<<<32, 256>>>((const float*)d_in[6]);
    autoint_mma<<<Bn / 2, 256, SMEM_BYTES>>>(
        (const int*)d_in[0], (const float*)d_in[1],
        (const float*)d_in[7], (float*)d_out);
}